// round 7
// baseline (speedup 1.0000x reference)
#include <cuda_runtime.h>
#include <cuda_fp16.h>
#include <cstdint>

#define SLOPE 0.1f
#define EPS 1e-5f

typedef unsigned long long ull;

constexpr int B    = 2;
constexpr int N    = 40960;
constexpr int K    = 16;
constexpr int C    = 64;
constexpr int CIN  = 74;   // C + 10 rel features
constexpr int XST  = 18;   // Xs stride in floats ([c][k] layout)
constexpr int OGST = 20;   // floats per og block in dup'd weights (16 used + 4 pad -> 80B)
constexpr int WDST = 160;  // floats per c row in dup'd weights (8 og * 20)
constexpr int OUT  = 64;
constexpr int SLOTS = 32;
constexpr int PPB1 = 32;   // points per block, kernel 1 (8 passes x 4 points)
constexpr int PPB3 = 32;   // points per block, kernel 3

// dynamic smem partition sizes (floats)
constexpr int K1_WD   = CIN * WDST;          // 11840
constexpr int K1_XS   = 4 * CIN * XST;       // 5328
constexpr size_t K1_SMEM = (size_t)(K1_WD + K1_XS) * 4 + 64 * 4 + 16 * 4;  // 68,992 B

constexpr int K3_WSD  = OUT * WDST;          // 10240
constexpr int K3_WMS  = OUT * 65;            // 4160
constexpr int K3_X1   = 4 * OUT * XST;       // 4608
constexpr size_t K3_SMEM = (size_t)(K3_WSD + K3_WMS + K3_X1 + 4 * OUT + 2 * OUT) * 4;  // 77,568 B

// ---------------- device scratch (static; no allocation) ----------------
__device__ float  g_featT[(size_t)B * N * C];              // 21 MB  (B,N,C)
__device__ __half g_z1h[(size_t)B * N * K * OUT];          // 160 MiB pre-BN mlp1, [pt][o][k] fp16
__device__ float  g_bn1s[SLOTS][OUT];
__device__ float  g_bn1q[SLOTS][OUT];
__device__ float  g_bn2s[SLOTS][OUT];
__device__ float  g_bn2q[SLOTS][OUT];
__device__ float  g_scale1[OUT], g_bias1[OUT];
__device__ float  g_scale2[OUT], g_bias2[OUT];

// -------- packed f32x2 helpers --------
__device__ __forceinline__ void fma2(ull& acc, ull a, ull b) {
    asm("fma.rn.f32x2 %0, %1, %2, %0;" : "+l"(acc) : "l"(a), "l"(b));
}
__device__ __forceinline__ void unpack2(ull v, float& lo, float& hi) {
    asm("mov.b64 {%0, %1}, %2;" : "=f"(lo), "=f"(hi) : "l"(v));
}

// ---------------- zero BN partials ----------------
__global__ void k_zero() {
    int t = blockIdx.x * blockDim.x + threadIdx.x;
    if (t < SLOTS * OUT) {
        ((float*)g_bn1s)[t] = 0.f;
        ((float*)g_bn1q)[t] = 0.f;
        ((float*)g_bn2s)[t] = 0.f;
        ((float*)g_bn2q)[t] = 0.f;
    }
}

// ---------------- transpose feat (B,C,N) -> (B,N,C) ----------------
__global__ void k_trans(const float* __restrict__ feat) {
    __shared__ float tile[32][33];
    int b  = blockIdx.z;
    int c0 = blockIdx.y * 32;
    int n0 = blockIdx.x * 32;
    int tx = threadIdx.x, ty = threadIdx.y;
    #pragma unroll
    for (int j = ty; j < 32; j += 8)
        tile[j][tx] = feat[((size_t)b * C + (c0 + j)) * N + (n0 + tx)];
    __syncthreads();
    #pragma unroll
    for (int j = ty; j < 32; j += 8)
        g_featT[((size_t)b * N + (n0 + j)) * C + (c0 + tx)] = tile[tx][j];
}

// ---------------- kernel 1: gather + rel + W1 GEMM (8o x 4k FFMA2) + BN1 stats ----------------
__global__ void __launch_bounds__(128) k1(const float* __restrict__ xyz,
                                          const int*   __restrict__ nidx,
                                          const float* __restrict__ W1) {
    extern __shared__ __align__(16) char smemraw[];
    float* Wd   = (float*)smemraw;             // dup'd W1^T [c][og][jo-pair]  47.4 KB
    float* XsB  = Wd + K1_WD;                  // [4][c][k]                    21.3 KB
    int*   idxs = (int*)(XsB + K1_XS);         // [4][16]
    float* ctr  = (float*)(idxs + 64);         // [4][3] (pad to 16)

    const int t   = threadIdx.x;
    const int blk = blockIdx.x;
    const int blocksPerBatch = N / PPB1;   // 1280
    const int b  = blk / blocksPerBatch;
    const int n0 = (blk % blocksPerBatch) * PPB1;

    // fill dup'd weights: o = jo*8+og -> Wd[c*WDST + og*OGST + jo*2 + {0,1}]
    for (int i = t; i < OUT * CIN; i += 128) {
        int o = i / CIN, c = i % CIN;
        float w = W1[i];
        int base = c * WDST + (o & 7) * OGST + (o >> 3) * 2;
        Wd[base] = w; Wd[base + 1] = w;
    }

    const int kg = t & 3;           // k group (4 k each)
    const int og = (t >> 2) & 7;    // o group (8 o each, o = jo*8+og)
    const int pt = t >> 5;          // point within 4-point pass (== warp id)
    const int kbase = kg * 4;

    float sS[8], sQ[8];
    #pragma unroll
    for (int j = 0; j < 8; ++j) { sS[j] = 0.f; sQ[j] = 0.f; }

    for (int pass = 0; pass < PPB1 / 4; ++pass) {
        __syncthreads();   // prev pass fully consumed (also covers Wd fill on pass 0)
        if (t < 64) {
            int pp = t >> 4, k = t & 15;
            idxs[pp * K + k] = nidx[((size_t)b * N + (n0 + pass * 4 + pp)) * K + k];
        } else if (t < 80) {
            int pp = (t - 64) >> 2, d = (t - 64) & 3;
            if (d < 3)
                ctr[pp * 3 + d] = xyz[((size_t)b * N + (n0 + pass * 4 + pp)) * 3 + d];
        }
        __syncthreads();
        // gather neighbor feats (float4, coalesced) -> Xs[c][k]
        for (int i = t; i < 1024; i += 128) {
            int pp = i >> 8;
            int k  = (i >> 4) & 15;
            int c4 = i & 15;
            float4 v = *(const float4*)&g_featT[((size_t)b * N + idxs[pp * K + k]) * C + c4 * 4];
            float* X = &XsB[pp * CIN * XST + (c4 * 4) * XST + k];
            X[0] = v.x; X[XST] = v.y; X[2 * XST] = v.z; X[3 * XST] = v.w;
        }
        // relative position encoding (channels C..C+9)
        if (t < 64) {
            int pp = t >> 4, k = t & 15;
            int nb = idxs[pp * K + k];
            float nx = xyz[((size_t)b * N + nb) * 3 + 0];
            float ny = xyz[((size_t)b * N + nb) * 3 + 1];
            float nz = xyz[((size_t)b * N + nb) * 3 + 2];
            float cx = ctr[pp * 3 + 0], cy = ctr[pp * 3 + 1], cz = ctr[pp * 3 + 2];
            float dx = cx - nx, dy = cy - ny, dz = cz - nz;
            float dist = sqrtf(dx * dx + dy * dy + dz * dz);
            float* X = &XsB[pp * CIN * XST];
            X[(C + 0) * XST + k] = dx;  X[(C + 1) * XST + k] = dy;
            X[(C + 2) * XST + k] = dz;  X[(C + 3) * XST + k] = dist;
            X[(C + 4) * XST + k] = cx;  X[(C + 5) * XST + k] = cy;
            X[(C + 6) * XST + k] = cz;  X[(C + 7) * XST + k] = nx;
            X[(C + 8) * XST + k] = ny;  X[(C + 9) * XST + k] = nz;
        }
        __syncthreads();

        // 8(o) x 4(k) GEMM via fma.rn.f32x2; weights pre-duplicated
        ull aL[8], aH[8];
        #pragma unroll
        for (int j = 0; j < 8; ++j) { aL[j] = 0ull; aH[j] = 0ull; }
        const float* Xp = &XsB[pt * CIN * XST];
        #pragma unroll 2
        for (int c = 0; c < CIN; ++c) {
            ull x01 = *(const ull*)&Xp[c * XST + kbase];
            ull x23 = *(const ull*)&Xp[c * XST + kbase + 2];
            const float* wr = &Wd[c * WDST + og * OGST];
            #pragma unroll
            for (int j4 = 0; j4 < 4; ++j4) {
                ulonglong2 w = *(const ulonglong2*)&wr[j4 * 4];
                fma2(aL[2 * j4],     w.x, x01); fma2(aH[2 * j4],     w.x, x23);
                fma2(aL[2 * j4 + 1], w.y, x01); fma2(aH[2 * j4 + 1], w.y, x23);
            }
        }

        // fp16 store [pt][o][k] + stats
        int n = n0 + pass * 4 + pt;
        __half* zp = g_z1h + ((size_t)(b * N + n)) * (size_t)(OUT * K);
        #pragma unroll
        for (int jo = 0; jo < 8; ++jo) {
            float v0, v1, v2, v3;
            unpack2(aL[jo], v0, v1);
            unpack2(aH[jo], v2, v3);
            int o = jo * 8 + og;
            __half2 hv[2];
            hv[0] = __floats2half2_rn(v0, v1);
            hv[1] = __floats2half2_rn(v2, v3);
            *(uint2*)&zp[o * K + kbase] = *(uint2*)hv;
            sS[jo] += v0 + v1 + v2 + v3;
            sQ[jo] += v0 * v0 + v1 * v1 + v2 * v2 + v3 * v3;
        }
    }

    // reduce over kg lanes, then slotted atomics
    #pragma unroll
    for (int off = 1; off <= 2; off <<= 1) {
        #pragma unroll
        for (int j = 0; j < 8; ++j) {
            sS[j] += __shfl_xor_sync(0xffffffffu, sS[j], off);
            sQ[j] += __shfl_xor_sync(0xffffffffu, sQ[j], off);
        }
    }
    if (kg == 0) {
        int slot = blk & (SLOTS - 1);
        #pragma unroll
        for (int jo = 0; jo < 8; ++jo) {
            int o = jo * 8 + og;
            atomicAdd(&g_bn1s[slot][o], sS[jo]);
            atomicAdd(&g_bn1q[slot][o], sQ[jo]);
        }
    }
}

// ---------------- BN finalize (globals referenced directly) ----------------
__global__ void k_bnfin1(const float* __restrict__ g, const float* __restrict__ bb) {
    int o = threadIdx.x;
    float s = 0.f, q = 0.f;
    #pragma unroll
    for (int sl = 0; sl < SLOTS; ++sl) { s += g_bn1s[sl][o]; q += g_bn1q[sl][o]; }
    const float cnt = (float)((size_t)B * N * K);
    float mean = s / cnt;
    float var  = q / cnt - mean * mean;
    float rstd = rsqrtf(var + EPS);
    g_scale1[o] = rstd * g[o];
    g_bias1[o]  = bb[o] - mean * rstd * g[o];
}

__global__ void k_bnfin2(const float* __restrict__ g, const float* __restrict__ bb) {
    int o = threadIdx.x;
    float s = 0.f, q = 0.f;
    #pragma unroll
    for (int sl = 0; sl < SLOTS; ++sl) { s += g_bn2s[sl][o]; q += g_bn2q[sl][o]; }
    const float cnt = (float)((size_t)B * N);
    float mean = s / cnt;
    float var  = q / cnt - mean * mean;
    float rstd = rsqrtf(var + EPS);
    g_scale2[o] = rstd * g[o];
    g_bias2[o]  = bb[o] - mean * rstd * g[o];
}

// ---------------- kernel 3: BN1+lrelu, score GEMM (8x4 FFMA2), softmax-pool, Wm ----------------
__global__ void __launch_bounds__(128) k3(const float* __restrict__ Ws,
                                          const float* __restrict__ Wm,
                                          float* __restrict__ out) {
    extern __shared__ __align__(16) char smemraw[];
    float* Wsd = (float*)smemraw;        // dup'd Ws^T          40.9 KB
    float* Wms = Wsd + K3_WSD;           // Wm [o][c]           16.6 KB
    float* x1B = Wms + K3_WMS;           // x1 [4][c][k]        18.4 KB
    float* ps  = x1B + K3_X1;            // [4][OUT]
    float* scl = ps + 4 * OUT;
    float* bia = scl + OUT;

    const int t   = threadIdx.x;
    const int blk = blockIdx.x;
    const int blocksPerBatch = N / PPB3;
    const int b  = blk / blocksPerBatch;
    const int n0 = (blk % blocksPerBatch) * PPB3;

    for (int i = t; i < OUT * OUT; i += 128) {
        int o = i >> 6, c = i & 63;
        float w = Ws[i];
        int base = c * WDST + (o & 7) * OGST + (o >> 3) * 2;
        Wsd[base] = w; Wsd[base + 1] = w;
        Wms[o * 65 + c] = Wm[i];
    }
    if (t < OUT) { scl[t] = g_scale1[t]; bia[t] = g_bias1[t]; }

    const int kg = t & 3;
    const int og = (t >> 2) & 7;
    const int pt = t >> 5;
    const int kbase = kg * 4;
    const int lane5 = t & 31;

    float a2s0 = 0.f, a2q0 = 0.f, a2s1 = 0.f, a2q1 = 0.f;

    for (int pass = 0; pass < PPB3 / 4; ++pass) {
        __syncthreads();
        // stage: z1 fp16 -> BN1 -> lrelu -> x1s[c][k] fp32
        const uint2* src = (const uint2*)(g_z1h + ((size_t)(b * N + n0 + pass * 4)) * (size_t)(OUT * K));
        for (int j = t; j < 1024; j += 128) {
            int pp = j >> 8;
            int r  = j & 255;
            int o  = r >> 2;
            int kq = (r & 3) * 4;
            uint2 u = src[j];
            __half2 h01 = *(__half2*)&u.x;
            __half2 h23 = *(__half2*)&u.y;
            float2 f01 = __half22float2(h01);
            float2 f23 = __half22float2(h23);
            float s = scl[o], bs = bia[o];
            float y0 = fmaf(f01.x, s, bs); y0 = y0 >= 0.f ? y0 : SLOPE * y0;
            float y1 = fmaf(f01.y, s, bs); y1 = y1 >= 0.f ? y1 : SLOPE * y1;
            float y2 = fmaf(f23.x, s, bs); y2 = y2 >= 0.f ? y2 : SLOPE * y2;
            float y3 = fmaf(f23.y, s, bs); y3 = y3 >= 0.f ? y3 : SLOPE * y3;
            float* dst = &x1B[pp * OUT * XST + o * XST + kq];
            *(float2*)(dst)     = make_float2(y0, y1);
            *(float2*)(dst + 2) = make_float2(y2, y3);
        }
        __syncthreads();

        // packed score GEMM: S[o][k] = sum_c Ws[o][c] * x1[c][k]
        ull sL[8], sH[8];
        #pragma unroll
        for (int j = 0; j < 8; ++j) { sL[j] = 0ull; sH[j] = 0ull; }
        const float* Xp = &x1B[pt * OUT * XST];
        #pragma unroll 2
        for (int c = 0; c < OUT; ++c) {
            ull x01 = *(const ull*)&Xp[c * XST + kbase];
            ull x23 = *(const ull*)&Xp[c * XST + kbase + 2];
            const float* wr = &Wsd[c * WDST + og * OGST];
            #pragma unroll
            for (int j4 = 0; j4 < 4; ++j4) {
                ulonglong2 w = *(const ulonglong2*)&wr[j4 * 4];
                fma2(sL[2 * j4],     w.x, x01); fma2(sH[2 * j4],     w.x, x23);
                fma2(sL[2 * j4 + 1], w.y, x01); fma2(sH[2 * j4 + 1], w.y, x23);
            }
        }

        // softmax over K + weighted pooling (per jo, reduce over kg lanes)
        #pragma unroll
        for (int jo = 0; jo < 8; ++jo) {
            float s0, s1, s2, s3;
            unpack2(sL[jo], s0, s1);
            unpack2(sH[jo], s2, s3);
            int o = jo * 8 + og;
            float m = fmaxf(fmaxf(s0, s1), fmaxf(s2, s3));
            m = fmaxf(m, __shfl_xor_sync(0xffffffffu, m, 1));
            m = fmaxf(m, __shfl_xor_sync(0xffffffffu, m, 2));
            float e0 = __expf(s0 - m);
            float e1 = __expf(s1 - m);
            float e2 = __expf(s2 - m);
            float e3 = __expf(s3 - m);
            float den = e0 + e1 + e2 + e3;
            float2 xa = *(const float2*)&Xp[o * XST + kbase];
            float2 xb = *(const float2*)&Xp[o * XST + kbase + 2];
            float num = e0 * xa.x + e1 * xa.y + e2 * xb.x + e3 * xb.y;
            den += __shfl_xor_sync(0xffffffffu, den, 1);
            num += __shfl_xor_sync(0xffffffffu, num, 1);
            den += __shfl_xor_sync(0xffffffffu, den, 2);
            num += __shfl_xor_sync(0xffffffffu, num, 2);
            if (kg == 0) ps[pt * OUT + o] = num / den;
        }
        __syncthreads();

        // z2 = Wm @ p : 32 threads per point, 2 channels each
        {
            int n = n0 + pass * 4 + pt;
            #pragma unroll
            for (int h = 0; h < 2; ++h) {
                int o = lane5 + h * 32;
                float z2 = 0.f;
                #pragma unroll 8
                for (int c = 0; c < OUT; ++c)
                    z2 = fmaf(Wms[o * 65 + c], ps[pt * OUT + c], z2);
                out[((size_t)b * OUT + o) * N + n] = z2;   // raw pre-BN2
                if (h == 0) { a2s0 += z2; a2q0 += z2 * z2; }
                else        { a2s1 += z2; a2q1 += z2 * z2; }
            }
        }
    }

    int slot = blk & (SLOTS - 1);
    atomicAdd(&g_bn2s[slot][lane5],      a2s0);
    atomicAdd(&g_bn2q[slot][lane5],      a2q0);
    atomicAdd(&g_bn2s[slot][lane5 + 32], a2s1);
    atomicAdd(&g_bn2q[slot][lane5 + 32], a2q1);
}

// ---------------- kernel 5: BN2 + LeakyReLU in place (vectorized) ----------------
__global__ void k5(float* __restrict__ out) {
    int i = blockIdx.x * blockDim.x + threadIdx.x;
    if (i < B * OUT * N / 4) {
        int o = (i * 4 / N) & (OUT - 1);
        float s = g_scale2[o], bs = g_bias2[o];
        float4 v = ((float4*)out)[i];
        v.x = fmaf(v.x, s, bs); v.x = v.x >= 0.f ? v.x : SLOPE * v.x;
        v.y = fmaf(v.y, s, bs); v.y = v.y >= 0.f ? v.y : SLOPE * v.y;
        v.z = fmaf(v.z, s, bs); v.z = v.z >= 0.f ? v.z : SLOPE * v.z;
        v.w = fmaf(v.w, s, bs); v.w = v.w >= 0.f ? v.w : SLOPE * v.w;
        ((float4*)out)[i] = v;
    }
}

// ---------------- launch ----------------
extern "C" void kernel_launch(void* const* d_in, const int* in_sizes, int n_in,
                              void* d_out, int out_size) {
    const float* xyz  = (const float*)d_in[0];
    const float* feat = (const float*)d_in[1];
    const int*   nidx = (const int*)d_in[2];
    const float* W1   = (const float*)d_in[3];
    const float* g1   = (const float*)d_in[4];
    const float* b1   = (const float*)d_in[5];
    const float* Ws   = (const float*)d_in[6];
    const float* Wm   = (const float*)d_in[7];
    const float* g2   = (const float*)d_in[8];
    const float* b2   = (const float*)d_in[9];
    float* out = (float*)d_out;

    // raise dynamic smem limits (host API, not stream-ordered; first harness call
    // is the uncaptured correctness run, so attributes are set before capture and
    // persist for module lifetime)
    cudaFuncSetAttribute(k1, cudaFuncAttributeMaxDynamicSharedMemorySize, (int)K1_SMEM);
    cudaFuncSetAttribute(k3, cudaFuncAttributeMaxDynamicSharedMemorySize, (int)K3_SMEM);

    k_zero<<<(SLOTS * OUT + 255) / 256, 256>>>();
    k_trans<<<dim3(N / 32, C / 32, B), dim3(32, 8)>>>(feat);
    k1<<<B * N / PPB1, 128, K1_SMEM>>>(xyz, nidx, W1);
    k_bnfin1<<<1, OUT>>>(g1, b1);
    k3<<<B * N / PPB3, 128, K3_SMEM>>>(Ws, Wm, out);
    k_bnfin2<<<1, OUT>>>(g2, b2);
    k5<<<(B * OUT * N / 4 + 255) / 256, 256>>>(out);
}

// round 8
// speedup vs baseline: 1.3546x; 1.3546x over previous
#include <cuda_runtime.h>
#include <cuda_fp16.h>
#include <cstdint>

#define SLOPE 0.1f
#define EPS 1e-5f

typedef unsigned long long ull;

constexpr int B    = 2;
constexpr int N    = 40960;
constexpr int K    = 16;
constexpr int C    = 64;
constexpr int CIN  = 74;   // C + 10 rel features
constexpr int XST  = 20;   // Xs stride in floats ([c][k] layout, 80B rows, 16B-aligned)
constexpr int WST  = 68;   // weight stride in floats ([c][o] layout, 272B rows, 16B-aligned)
constexpr int OUT  = 64;
constexpr int SLOTS = 32;
constexpr int PPB1 = 16;   // points per block (8 passes x 2 points)
constexpr int PPB3 = 16;

// ---------------- device scratch (static; no allocation) ----------------
__device__ float  g_featT[(size_t)B * N * C];              // 21 MB (B,N,C)
__device__ __half g_z1h[(size_t)B * N * K * OUT];          // 160 MiB pre-BN mlp1, [pt][o][k] fp16
__device__ float  g_bn1s[SLOTS][OUT];
__device__ float  g_bn1q[SLOTS][OUT];
__device__ float  g_bn2s[SLOTS][OUT];
__device__ float  g_bn2q[SLOTS][OUT];
__device__ float  g_scale1[OUT], g_bias1[OUT];
__device__ float  g_scale2[OUT], g_bias2[OUT];

// -------- packed f32x2 helpers --------
__device__ __forceinline__ void fma2(ull& acc, ull a, ull b) {
    asm("fma.rn.f32x2 %0, %1, %2, %0;" : "+l"(acc) : "l"(a), "l"(b));
}
__device__ __forceinline__ ull dup2(float w) {
    ull r;
    asm("mov.b64 %0, {%1, %1};" : "=l"(r) : "f"(w));
    return r;
}
__device__ __forceinline__ void unpack2(ull v, float& lo, float& hi) {
    asm("mov.b64 {%0, %1}, %2;" : "=f"(lo), "=f"(hi) : "l"(v));
}

// ---------------- zero BN partials ----------------
__global__ void k_zero() {
    int t = blockIdx.x * blockDim.x + threadIdx.x;
    if (t < SLOTS * OUT) {
        ((float*)g_bn1s)[t] = 0.f;
        ((float*)g_bn1q)[t] = 0.f;
        ((float*)g_bn2s)[t] = 0.f;
        ((float*)g_bn2q)[t] = 0.f;
    }
}

// ---------------- transpose feat (B,C,N) -> (B,N,C) ----------------
__global__ void k_trans(const float* __restrict__ feat) {
    __shared__ float tile[32][33];
    int b  = blockIdx.z;
    int c0 = blockIdx.y * 32;
    int n0 = blockIdx.x * 32;
    int tx = threadIdx.x, ty = threadIdx.y;
    #pragma unroll
    for (int j = ty; j < 32; j += 8)
        tile[j][tx] = feat[((size_t)b * C + (c0 + j)) * N + (n0 + tx)];
    __syncthreads();
    #pragma unroll
    for (int j = ty; j < 32; j += 8)
        g_featT[((size_t)b * N + (n0 + j)) * C + (c0 + tx)] = tile[tx][j];
}

// ---------------- kernel 1: gather + rel + W1 GEMM (o-packed FFMA2) + BN1 stats ----------------
__global__ void __launch_bounds__(128) k1(const float* __restrict__ xyz,
                                          const int*   __restrict__ nidx,
                                          const float* __restrict__ W1) {
    __shared__ __align__(16) float W1t[CIN * WST];      // [c][o]  20.1 KB
    __shared__ __align__(16) float Xs[2][CIN * XST];    // [c][k]  11.8 KB
    __shared__ int   idxs[2][K];
    __shared__ float ctr[2][3];

    const int t   = threadIdx.x;
    const int blk = blockIdx.x;
    const int blocksPerBatch = N / PPB1;   // 2560
    const int b  = blk / blocksPerBatch;
    const int n0 = (blk % blocksPerBatch) * PPB1;

    // W1 [o][c] -> W1t [c][o]
    for (int i = t; i < OUT * CIN; i += 128) {
        int o = i / CIN, c = i % CIN;
        W1t[c * WST + o] = W1[i];
    }

    const int p_loc = t >> 6;          // point within pair
    const int tt    = t & 63;
    const int kg    = tt & 3;          // 4 k per thread
    const int og    = tt >> 2;         // 16 o-groups of 4
    const int obase = og * 4;
    const int kbase = kg * 4;

    float accS0 = 0.f, accS1 = 0.f, accS2 = 0.f, accS3 = 0.f;
    float accQ0 = 0.f, accQ1 = 0.f, accQ2 = 0.f, accQ3 = 0.f;

    for (int pair = 0; pair < PPB1 / 2; ++pair) {
        __syncthreads();
        if (t < 32) {
            int pp = t >> 4, k = t & 15;
            int n  = n0 + pair * 2 + pp;
            idxs[pp][k] = nidx[((size_t)b * N + n) * K + k];
        }
        if (t >= 32 && t < 40) {
            int pp = (t - 32) >> 2, d = (t - 32) & 3;
            if (d < 3) {
                int n = n0 + pair * 2 + pp;
                ctr[pp][d] = xyz[((size_t)b * N + n) * 3 + d];
            }
        }
        __syncthreads();
        // gather neighbor feats: lane -> (c4, pp, k); float4 gmem read, 4 smem writes
        for (int i = t; i < 512; i += 128) {
            int k  = i & 15;
            int pp = (i >> 4) & 1;
            int c4 = i >> 5;
            float4 v = *(const float4*)&g_featT[((size_t)b * N + idxs[pp][k]) * C + c4 * 4];
            float* X = &Xs[pp][(c4 * 4) * XST + k];
            X[0] = v.x; X[XST] = v.y; X[2 * XST] = v.z; X[3 * XST] = v.w;
        }
        // relative position encoding (channels C..C+9)
        if (t < 32) {
            int pp = t >> 4, k = t & 15;
            int nb = idxs[pp][k];
            float nx = xyz[((size_t)b * N + nb) * 3 + 0];
            float ny = xyz[((size_t)b * N + nb) * 3 + 1];
            float nz = xyz[((size_t)b * N + nb) * 3 + 2];
            float cx = ctr[pp][0], cy = ctr[pp][1], cz = ctr[pp][2];
            float dx = cx - nx, dy = cy - ny, dz = cz - nz;
            float dist = sqrtf(dx * dx + dy * dy + dz * dz);
            float* X = Xs[pp];
            X[(C + 0) * XST + k] = dx;  X[(C + 1) * XST + k] = dy;
            X[(C + 2) * XST + k] = dz;  X[(C + 3) * XST + k] = dist;
            X[(C + 4) * XST + k] = cx;  X[(C + 5) * XST + k] = cy;
            X[(C + 6) * XST + k] = cz;  X[(C + 7) * XST + k] = nx;
            X[(C + 8) * XST + k] = ny;  X[(C + 9) * XST + k] = nz;
        }
        __syncthreads();

        // o-packed 4(o) x 4(k) GEMM: acc holds (o_even, o_odd) pairs
        ull a01[4] = {0ull, 0ull, 0ull, 0ull};   // (obase, obase+1) x k
        ull a23[4] = {0ull, 0ull, 0ull, 0ull};   // (obase+2, obase+3) x k
        const float* Xp = Xs[p_loc];
        #pragma unroll 2
        for (int c = 0; c < CIN; ++c) {
            float4 xv = *(const float4*)&Xp[c * XST + kbase];
            ulonglong2 w = *(const ulonglong2*)&W1t[c * WST + obase];
            ull xd0 = dup2(xv.x), xd1 = dup2(xv.y), xd2 = dup2(xv.z), xd3 = dup2(xv.w);
            fma2(a01[0], w.x, xd0); fma2(a23[0], w.y, xd0);
            fma2(a01[1], w.x, xd1); fma2(a23[1], w.y, xd1);
            fma2(a01[2], w.x, xd2); fma2(a23[2], w.y, xd2);
            fma2(a01[3], w.x, xd3); fma2(a23[3], w.y, xd3);
        }

        // unpack to v[jo][k]
        float v[4][4];
        #pragma unroll
        for (int k = 0; k < 4; ++k) {
            unpack2(a01[k], v[0][k], v[1][k]);
            unpack2(a23[k], v[2][k], v[3][k]);
        }

        // fp16 store [pt][o][k] + BN1 stats
        int n = n0 + pair * 2 + p_loc;
        __half* zp = g_z1h + ((size_t)(b * N + n)) * (size_t)(OUT * K);
        #pragma unroll
        for (int jo = 0; jo < 4; ++jo) {
            int o = obase + jo;
            __half2 hv[2];
            hv[0] = __floats2half2_rn(v[jo][0], v[jo][1]);
            hv[1] = __floats2half2_rn(v[jo][2], v[jo][3]);
            *(uint2*)&zp[o * K + kbase] = *(uint2*)hv;
            float s = v[jo][0] + v[jo][1] + v[jo][2] + v[jo][3];
            float q = v[jo][0] * v[jo][0] + v[jo][1] * v[jo][1]
                    + v[jo][2] * v[jo][2] + v[jo][3] * v[jo][3];
            if (jo == 0) { accS0 += s; accQ0 += q; }
            else if (jo == 1) { accS1 += s; accQ1 += q; }
            else if (jo == 2) { accS2 += s; accQ2 += q; }
            else { accS3 += s; accQ3 += q; }
        }
    }

    // reduce over kg lanes, then slotted atomics
    #pragma unroll
    for (int off = 1; off <= 2; off <<= 1) {
        accS0 += __shfl_xor_sync(0xffffffffu, accS0, off);
        accQ0 += __shfl_xor_sync(0xffffffffu, accQ0, off);
        accS1 += __shfl_xor_sync(0xffffffffu, accS1, off);
        accQ1 += __shfl_xor_sync(0xffffffffu, accQ1, off);
        accS2 += __shfl_xor_sync(0xffffffffu, accS2, off);
        accQ2 += __shfl_xor_sync(0xffffffffu, accQ2, off);
        accS3 += __shfl_xor_sync(0xffffffffu, accS3, off);
        accQ3 += __shfl_xor_sync(0xffffffffu, accQ3, off);
    }
    if (kg == 0) {
        int slot = blk & (SLOTS - 1);
        atomicAdd(&g_bn1s[slot][obase + 0], accS0);
        atomicAdd(&g_bn1q[slot][obase + 0], accQ0);
        atomicAdd(&g_bn1s[slot][obase + 1], accS1);
        atomicAdd(&g_bn1q[slot][obase + 1], accQ1);
        atomicAdd(&g_bn1s[slot][obase + 2], accS2);
        atomicAdd(&g_bn1q[slot][obase + 2], accQ2);
        atomicAdd(&g_bn1s[slot][obase + 3], accS3);
        atomicAdd(&g_bn1q[slot][obase + 3], accQ3);
    }
}

// ---------------- BN finalize (globals referenced directly) ----------------
__global__ void k_bnfin1(const float* __restrict__ g, const float* __restrict__ bb) {
    int o = threadIdx.x;
    float s = 0.f, q = 0.f;
    #pragma unroll
    for (int sl = 0; sl < SLOTS; ++sl) { s += g_bn1s[sl][o]; q += g_bn1q[sl][o]; }
    const float cnt = (float)((size_t)B * N * K);
    float mean = s / cnt;
    float var  = q / cnt - mean * mean;
    float rstd = rsqrtf(var + EPS);
    g_scale1[o] = rstd * g[o];
    g_bias1[o]  = bb[o] - mean * rstd * g[o];
}

__global__ void k_bnfin2(const float* __restrict__ g, const float* __restrict__ bb) {
    int o = threadIdx.x;
    float s = 0.f, q = 0.f;
    #pragma unroll
    for (int sl = 0; sl < SLOTS; ++sl) { s += g_bn2s[sl][o]; q += g_bn2q[sl][o]; }
    const float cnt = (float)((size_t)B * N);
    float mean = s / cnt;
    float var  = q / cnt - mean * mean;
    float rstd = rsqrtf(var + EPS);
    g_scale2[o] = rstd * g[o];
    g_bias2[o]  = bb[o] - mean * rstd * g[o];
}

// ---------------- kernel 3: BN1+lrelu, score GEMM (o-packed FFMA2), softmax-pool, Wm ----------------
__global__ void __launch_bounds__(128) k3(const float* __restrict__ Ws,
                                          const float* __restrict__ Wm,
                                          float* __restrict__ out) {
    __shared__ __align__(16) float Wst[OUT * WST];      // Ws^T [c][o] 17.4 KB
    __shared__ float Wms[OUT * 65];                     // Wm [o][c]   16.6 KB
    __shared__ __align__(16) float x1s[2][OUT * XST];   // x1 [c][k]   10.2 KB
    __shared__ float ps[2][OUT];
    __shared__ float scl[OUT], bia[OUT];

    const int t   = threadIdx.x;
    const int blk = blockIdx.x;
    const int blocksPerBatch = N / PPB3;
    const int b  = blk / blocksPerBatch;
    const int n0 = (blk % blocksPerBatch) * PPB3;

    for (int i = t; i < OUT * OUT; i += 128) {
        int o = i >> 6, c = i & 63;
        Wst[c * WST + o] = Ws[i];
        Wms[o * 65 + c]  = Wm[i];
    }
    if (t < OUT) { scl[t] = g_scale1[t]; bia[t] = g_bias1[t]; }

    const int p_loc = t >> 6;
    const int tt    = t & 63;
    const int kg    = tt & 3;
    const int og    = tt >> 2;
    const int obase = og * 4;
    const int kbase = kg * 4;

    float a2s = 0.f, a2q = 0.f;

    for (int pair = 0; pair < PPB3 / 2; ++pair) {
        __syncthreads();
        // z1 fp16 load (uint2, coalesced) -> BN1 -> lrelu -> x1s[c][k]
        const uint2* src = (const uint2*)(g_z1h + ((size_t)(b * N + n0 + pair * 2)) * (size_t)(OUT * K));
        for (int j = t; j < 512; j += 128) {
            int pp = j >> 8;
            int r  = j & 255;
            int o  = r >> 2;
            int kq = (r & 3) * 4;
            uint2 u = src[j];
            float2 f01 = __half22float2(*(__half2*)&u.x);
            float2 f23 = __half22float2(*(__half2*)&u.y);
            float s = scl[o], bs = bia[o];
            float y0 = fmaf(f01.x, s, bs); y0 = y0 >= 0.f ? y0 : SLOPE * y0;
            float y1 = fmaf(f01.y, s, bs); y1 = y1 >= 0.f ? y1 : SLOPE * y1;
            float y2 = fmaf(f23.x, s, bs); y2 = y2 >= 0.f ? y2 : SLOPE * y2;
            float y3 = fmaf(f23.y, s, bs); y3 = y3 >= 0.f ? y3 : SLOPE * y3;
            float* dst = &x1s[pp][o * XST + kq];
            *(float2*)(dst)     = make_float2(y0, y1);
            *(float2*)(dst + 2) = make_float2(y2, y3);
        }
        __syncthreads();

        // o-packed score GEMM: S[o][k] = sum_c Ws[o][c] * x1[c][k]
        ull a01[4] = {0ull, 0ull, 0ull, 0ull};
        ull a23[4] = {0ull, 0ull, 0ull, 0ull};
        const float* Xp = x1s[p_loc];
        #pragma unroll 2
        for (int c = 0; c < OUT; ++c) {
            float4 xv = *(const float4*)&Xp[c * XST + kbase];
            ulonglong2 w = *(const ulonglong2*)&Wst[c * WST + obase];
            ull xd0 = dup2(xv.x), xd1 = dup2(xv.y), xd2 = dup2(xv.z), xd3 = dup2(xv.w);
            fma2(a01[0], w.x, xd0); fma2(a23[0], w.y, xd0);
            fma2(a01[1], w.x, xd1); fma2(a23[1], w.y, xd1);
            fma2(a01[2], w.x, xd2); fma2(a23[2], w.y, xd2);
            fma2(a01[3], w.x, xd3); fma2(a23[3], w.y, xd3);
        }

        float v[4][4];
        #pragma unroll
        for (int k = 0; k < 4; ++k) {
            unpack2(a01[k], v[0][k], v[1][k]);
            unpack2(a23[k], v[2][k], v[3][k]);
        }

        // softmax over K + weighted pooling
        #pragma unroll
        for (int jo = 0; jo < 4; ++jo) {
            int o = obase + jo;
            float s0 = v[jo][0], s1 = v[jo][1], s2 = v[jo][2], s3 = v[jo][3];
            float m = fmaxf(fmaxf(s0, s1), fmaxf(s2, s3));
            m = fmaxf(m, __shfl_xor_sync(0xffffffffu, m, 1));
            m = fmaxf(m, __shfl_xor_sync(0xffffffffu, m, 2));
            float e0 = __expf(s0 - m);
            float e1 = __expf(s1 - m);
            float e2 = __expf(s2 - m);
            float e3 = __expf(s3 - m);
            float den = e0 + e1 + e2 + e3;
            float4 xo = *(const float4*)&Xp[o * XST + kbase];
            float num = e0 * xo.x + e1 * xo.y + e2 * xo.z + e3 * xo.w;
            den += __shfl_xor_sync(0xffffffffu, den, 1);
            num += __shfl_xor_sync(0xffffffffu, num, 1);
            den += __shfl_xor_sync(0xffffffffu, den, 2);
            num += __shfl_xor_sync(0xffffffffu, num, 2);
            if (kg == 0) ps[p_loc][o] = num / den;
        }
        __syncthreads();

        // z2 = Wm @ p  (one (point, channel) per thread)
        {
            int o  = t & 63;
            int pp = t >> 6;
            float z2 = 0.f;
            #pragma unroll 8
            for (int c = 0; c < OUT; ++c)
                z2 = fmaf(Wms[o * 65 + c], ps[pp][c], z2);
            int n = n0 + pair * 2 + pp;
            out[((size_t)b * OUT + o) * N + n] = z2;   // raw pre-BN2
            a2s += z2;
            a2q += z2 * z2;
        }
    }

    int slot = blk & (SLOTS - 1);
    atomicAdd(&g_bn2s[slot][t & 63], a2s);
    atomicAdd(&g_bn2q[slot][t & 63], a2q);
}

// ---------------- kernel 5: BN2 + LeakyReLU in place (vectorized) ----------------
__global__ void k5(float* __restrict__ out) {
    int i = blockIdx.x * blockDim.x + threadIdx.x;
    if (i < B * OUT * N / 4) {
        int o = (i * 4 / N) & (OUT - 1);
        float s = g_scale2[o], bs = g_bias2[o];
        float4 v = ((float4*)out)[i];
        v.x = fmaf(v.x, s, bs); v.x = v.x >= 0.f ? v.x : SLOPE * v.x;
        v.y = fmaf(v.y, s, bs); v.y = v.y >= 0.f ? v.y : SLOPE * v.y;
        v.z = fmaf(v.z, s, bs); v.z = v.z >= 0.f ? v.z : SLOPE * v.z;
        v.w = fmaf(v.w, s, bs); v.w = v.w >= 0.f ? v.w : SLOPE * v.w;
        ((float4*)out)[i] = v;
    }
}

// ---------------- launch ----------------
extern "C" void kernel_launch(void* const* d_in, const int* in_sizes, int n_in,
                              void* d_out, int out_size) {
    const float* xyz  = (const float*)d_in[0];
    const float* feat = (const float*)d_in[1];
    const int*   nidx = (const int*)d_in[2];
    const float* W1   = (const float*)d_in[3];
    const float* g1   = (const float*)d_in[4];
    const float* b1   = (const float*)d_in[5];
    const float* Ws   = (const float*)d_in[6];
    const float* Wm   = (const float*)d_in[7];
    const float* g2   = (const float*)d_in[8];
    const float* b2   = (const float*)d_in[9];
    float* out = (float*)d_out;

    k_zero<<<(SLOTS * OUT + 255) / 256, 256>>>();
    k_trans<<<dim3(N / 32, C / 32, B), dim3(32, 8)>>>(feat);
    k1<<<B * N / PPB1, 128>>>(xyz, nidx, W1);
    k_bnfin1<<<1, OUT>>>(g1, b1);
    k3<<<B * N / PPB3, 128>>>(Ws, Wm, out);
    k_bnfin2<<<1, OUT>>>(g2, b2);
    k5<<<(B * OUT * N / 4 + 255) / 256, 256>>>(out);
}